// round 15
// baseline (speedup 1.0000x reference)
#include <cuda_runtime.h>
#include <cuda_bf16.h>
#include <cstdint>

// ---------------- constants ----------------
#define NEGV -1e9f
#define TINYF 1.17549435e-38f

// ---------------- device scratch (static allocation only) ----------------
__device__ float g_inwT[128 * 128];     // in_w^T   [k][h]
__device__ float g_wihT[128 * 384];     // w_ih^T   [k][j]
__device__ float g_whhT[128 * 384];     // w_hh^T   [k][j]
__device__ float g_w1T [128 * 128];     // W_att[:,0:128]^T   [k][a]
__device__ float g_w3T [128 * 128];     // W_att[:,256:384]^T [k][a]
__device__ float g_M   [128 * 2];       // W2 @ dyn_w   [a][d]
__device__ float g_c2  [128];           // W2 @ dyn_b   [a]
__device__ unsigned g_fk0[64], g_fk1[64];
__device__ float g_X [256 * 64 * 128];  // x_t  [b][t][h]
__device__ float g_GI[256 * 64 * 384];  // gi_t [b][t][j]
__device__ float g_P [256 * 64 * 128];  // [b][s][a] step-invariant attention pre-act
__device__ float g_G [64 * 256 * 64];   // [t][b][s] gumbel term  (-log(-log(u)))

// ---------------- threefry-2x32 (20 rounds, JAX-exact) ----------------
__device__ __forceinline__ unsigned rotl32(unsigned x, int r) {
    return (x << r) | (x >> (32 - r));
}
__device__ __forceinline__ void tf2x32(unsigned k0, unsigned k1,
                                       unsigned x0, unsigned x1,
                                       unsigned& o0, unsigned& o1) {
    unsigned k2 = k0 ^ k1 ^ 0x1BD11BDAu;
    x0 += k0; x1 += k1;
    const int ra0 = 13, ra1 = 15, ra2 = 26, ra3 = 6;
    const int rb0 = 17, rb1 = 29, rb2 = 16, rb3 = 24;
#define TFR(r) { x0 += x1; x1 = rotl32(x1, r); x1 ^= x0; }
    TFR(ra0) TFR(ra1) TFR(ra2) TFR(ra3)
    x0 += k1; x1 += k2 + 1u;
    TFR(rb0) TFR(rb1) TFR(rb2) TFR(rb3)
    x0 += k2; x1 += k0 + 2u;
    TFR(ra0) TFR(ra1) TFR(ra2) TFR(ra3)
    x0 += k0; x1 += k1 + 3u;
    TFR(rb0) TFR(rb1) TFR(rb2) TFR(rb3)
    x0 += k1; x1 += k2 + 4u;
    TFR(ra0) TFR(ra1) TFR(ra2) TFR(ra3)
    x0 += k2; x1 += k0 + 5u;
#undef TFR
    o0 = x0; o1 = x1;
}

// ---------------- XLA-exact f32 tanh (Eigen rational) + logistic ----------------
__device__ __forceinline__ float xla_tanh(float x) {
    float ax = fabsf(x);
    float xc = fminf(fmaxf(x, -7.90531110763549805f), 7.90531110763549805f);
    float x2 = xc * xc;
    float p = fmaf(x2, -2.76076847742355e-16f, 2.00018790482477e-13f);
    p = fmaf(x2, p, -8.60467152213735e-11f);
    p = fmaf(x2, p,  5.12229709037114e-08f);
    p = fmaf(x2, p,  1.48572235717979e-05f);
    p = fmaf(x2, p,  6.37261928875436e-04f);
    p = fmaf(x2, p,  4.89352455891786e-03f);
    p = p * xc;
    float q = fmaf(x2, 1.19825839466702e-06f, 1.18534705686654e-04f);
    q = fmaf(x2, q, 2.26843463243900e-03f);
    q = fmaf(x2, q, 4.89352518554385e-03f);
    float r = __fdiv_rn(p, q);
    return (ax < 4.0e-4f) ? x : r;
}
__device__ __forceinline__ float xla_sigmoid(float x) {
    return 0.5f + 0.5f * xla_tanh(0.5f * x);
}

// ---------------- kernel 0: weight prep ----------------
__global__ void prep_kernel(const float* __restrict__ dyn_w, const float* __restrict__ dyn_b,
                            const float* __restrict__ in_w, const float* __restrict__ w_ih,
                            const float* __restrict__ w_hh, const float* __restrict__ W_att) {
    int tid = blockIdx.x * blockDim.x + threadIdx.x;
    int nt = gridDim.x * blockDim.x;
    for (int i = tid; i < 128 * 128; i += nt) {
        int h = i >> 7, k = i & 127;
        g_inwT[k * 128 + h] = in_w[i];
    }
    for (int i = tid; i < 384 * 128; i += nt) {
        int j = i >> 7, k = i & 127;
        g_wihT[k * 384 + j] = w_ih[i];
        g_whhT[k * 384 + j] = w_hh[i];
    }
    for (int i = tid; i < 128 * 128; i += nt) {
        int a = i >> 7, k = i & 127;
        g_w1T[k * 128 + a] = W_att[a * 384 + k];
        g_w3T[k * 128 + a] = W_att[a * 384 + 256 + k];
    }
    for (int i = tid; i < 128 * 2; i += nt) {
        int a = i >> 1, d = i & 1;
        float s = 0.f;
        for (int k = 0; k < 128; k++) s = fmaf(W_att[a * 384 + 128 + k], dyn_w[k * 2 + d], s);
        g_M[i] = s;
    }
    for (int i = tid; i < 128; i += nt) {
        float s = 0.f;
        for (int k = 0; k < 128; k++) s = fmaf(W_att[i * 384 + 128 + k], dyn_b[k], s);
        g_c2[i] = s;
    }
    if (tid < 64) {
        unsigned o0, o1;
        tf2x32(0u, 42u, 0u, (unsigned)tid, o0, o1);  // fold_in(key(42), t)
        g_fk0[tid] = o0; g_fk1[tid] = o1;
    }
}

// ---------------- kernel 0b: gumbel precompute (mask-independent) ----------------
__global__ void gumbel_kernel() {
    int i = blockIdx.x * blockDim.x + threadIdx.x;    // 0 .. 1048575
    int t = i >> 14;
    unsigned bs = (unsigned)(i & 16383);              // counter = b*64 + s
    unsigned o0, o1;
    tf2x32(g_fk0[t], g_fk1[t], 0u, bs, o0, o1);
    unsigned bits = o0 ^ o1;
    float f = __uint_as_float((bits >> 9) | 0x3f800000u) - 1.0f;
    float u = (f == 0.f) ? TINYF : f;
    float l1 = (float)log((double)u);
    float l2 = (float)log((double)(-l1));
    g_G[i] = -l2;                                     // z = logit + g_G  (== logit - l2)
}

// ---------------- kernel 1: x-chain (in_w SMEM-resident) ----------------
__global__ void xchain_kernel(const float* __restrict__ E, const float* __restrict__ in_b) {
    extern __shared__ float sw[];        // 16384 floats = 64KB inwT copy
    __shared__ float xs[128];
    int b = blockIdx.x;
    int h = threadIdx.x;                 // 128 threads
    for (int i = h; i < 16384; i += 128) sw[i] = g_inwT[i];
    xs[h] = E[b * 8192 + h * 64 + 0];    // static_embeddings[b, h, 0]
    float bb = in_b[h];
    __syncthreads();
    for (int t = 0; t < 64; t++) {
        float acc = bb;
        #pragma unroll 8
        for (int k = 0; k < 128; k++) acc = fmaf(sw[k * 128 + h], xs[k], acc);
        __syncthreads();
        xs[h] = acc;
        g_X[(b * 64 + t) * 128 + h] = acc;
        __syncthreads();
    }
}

// ---------------- kernel 2: GI = X @ w_ih^T + b_ih  (grid 256 x 6) ----------------
__global__ void gi_kernel(const float* __restrict__ b_ih) {
    __shared__ float Xs[64 * 128];
    int blk = blockIdx.x;
    int c   = blockIdx.y;
    for (int i = threadIdx.x; i < 8192; i += 256) Xs[i] = g_X[blk * 8192 + i];
    __syncthreads();
    int jl = threadIdx.x & 63;
    int btb = (threadIdx.x >> 6) * 16;
    int j = jl + 64 * c;
    float acc[16];
    #pragma unroll
    for (int r = 0; r < 16; r++) acc[r] = 0.f;
    for (int k = 0; k < 128; k += 4) {
        float w0 = g_wihT[(k + 0) * 384 + j];
        float w1 = g_wihT[(k + 1) * 384 + j];
        float w2 = g_wihT[(k + 2) * 384 + j];
        float w3 = g_wihT[(k + 3) * 384 + j];
        #pragma unroll
        for (int r = 0; r < 16; r++) {
            float4 x = *(const float4*)&Xs[(btb + r) * 128 + k];
            acc[r] = fmaf(w0, x.x, acc[r]);   // ascending k per accumulator
            acc[r] = fmaf(w1, x.y, acc[r]);
            acc[r] = fmaf(w2, x.z, acc[r]);
            acc[r] = fmaf(w3, x.w, acc[r]);
        }
    }
    float bb = b_ih[j];
    #pragma unroll
    for (int r = 0; r < 16; r++)
        g_GI[(size_t)(blk * 64 + btb + r) * 384 + j] = acc[r] + bb;
}

// ---------------- kernel 3: P[b][s][a] (grid 256 x 2) ----------------
__global__ void p_kernel(const float* __restrict__ E, const float* __restrict__ dyn) {
    __shared__ float Es[128 * 32];
    int b = blockIdx.x;
    int sh = blockIdx.y;                     // s half (0/1)
    for (int i = threadIdx.x; i < 4096; i += 256) {
        int k = i >> 5, s2 = i & 31;
        Es[i] = E[b * 8192 + k * 64 + sh * 32 + s2];
    }
    __syncthreads();
    int a = threadIdx.x & 127;
    int sq = (threadIdx.x >> 7) * 16;        // 16 s per thread
    float acc[16];
    #pragma unroll
    for (int ss = 0; ss < 16; ss++) acc[ss] = 0.f;
    for (int k = 0; k < 128; k++) {
        float w = g_w1T[k * 128 + a];
        const float4* e4 = (const float4*)&Es[k * 32 + sq];
        #pragma unroll
        for (int q = 0; q < 4; q++) {
            float4 e = e4[q];
            acc[q * 4 + 0] = fmaf(w, e.x, acc[q * 4 + 0]);
            acc[q * 4 + 1] = fmaf(w, e.y, acc[q * 4 + 1]);
            acc[q * 4 + 2] = fmaf(w, e.z, acc[q * 4 + 2]);
            acc[q * 4 + 3] = fmaf(w, e.w, acc[q * 4 + 3]);
        }
    }
    float m0 = g_M[a * 2], m1 = g_M[a * 2 + 1], c = g_c2[a];
    #pragma unroll
    for (int ss = 0; ss < 16; ss++) {
        int s = sh * 32 + sq + ss;
        float v = acc[ss] + fmaf(m0, dyn[b * 128 + s], fmaf(m1, dyn[b * 128 + 64 + s], c));
        g_P[((size_t)b * 64 + s) * 128 + a] = v;
    }
}

// ---------------- kernel 4: sequential decode (2 batches/CTA, 512 threads) ----------------
// Per-step schedule (3 barriers):
//   A : GRU_t (warps 0-7)  ||  prefetch GI_{t+1} + gumbel_t (warps 8-15); reset counters
//   BC: P1 gh_{t+1} (warps 0-11) and P2_t (warps 12-15, then publish gsm);
//       ALL warps then steal P3_t slots from a shared atomic counter (2 per grab)
//   D : P4a reductions; P4b overlaps next A
__global__ void __launch_bounds__(512, 1)
main_kernel(const float* __restrict__ b_hh, const float* __restrict__ v_att,
            float* __restrict__ out) {
    extern __shared__ float ws[];            // whhT copy: 49152 floats (196608 B)
    __shared__ float hs2[2 * 128];           // h interleaved: hs2[2*h + nb]
    __shared__ float ghs[2 * 384];
    __shared__ float gsm[2 * 128];
    __shared__ float sc[128];
    __shared__ float vsm[128];
    __shared__ float bhs[384];
    __shared__ float gis[2][768];            // double-buffered GI rows
    __shared__ float ggs[128];               // gumbel row for current step
    __shared__ int   vis[128];
    __shared__ int   lst[2][64];             // compacted active slot lists
    __shared__ int   pos[2][64];             // s -> list index
    __shared__ int   len_sm;
    __shared__ int   cnt2;                   // P3 slot steal counter
    __shared__ int   gsm_ready;              // P2 publication flag
    __shared__ float wbv[4], wml[4], wse[4];
    __shared__ int   wbi[4];

    int tid = threadIdx.x;
    int b0 = blockIdx.x * 2;

    for (int i = tid; i < 49152; i += 512) ws[i] = g_whhT[i];
    if (tid < 384) bhs[tid] = b_hh[tid];
    if (tid < 128) { vsm[tid] = v_att[tid]; vis[tid] = 0; }
    if (tid < 256) hs2[tid] = 0.f;
    if (tid < 2) { lst[tid][0] = 0; pos[tid][0] = 0; }
    if (tid == 0) len_sm = 1;                 // t=0: only s=0 active
    __syncthreads();                          // bhs visible
    // gh_0 = b_hh exactly (h0 = 0, fmaf(w,0,acc)=acc)
    if (tid < 384) { ghs[tid] = bhs[tid]; ghs[384 + tid] = bhs[tid]; }
    // preload gis[0] = GI rows at t=0
    for (int i = tid; i < 768; i += 512) {
        int nb = i >= 384; int j = i - nb * 384;
        gis[0][i] = g_GI[(((size_t)(b0 + nb) * 64) + 0) * 384 + j];
    }
    __syncthreads();

    const int wrp = tid >> 5, lane = tid & 31;
    const float v0 = vsm[lane], v1 = vsm[lane + 32], v2 = vsm[lane + 64], v3 = vsm[lane + 96];

    for (int t = 0; t < 64; t++) {
        // ======== Phase A: GRU_t (warps 0-7)  ||  prefetch (warps 8-15) ========
        if (tid < 256) {
            if (tid == 0) { cnt2 = 0; gsm_ready = 0; }
            int nb = tid >> 7, hh = tid & 127;
            const float* gi_ = &gis[t & 1][nb * 384];
            float ir = gi_[hh];
            float iz = gi_[128 + hh];
            float inn = gi_[256 + hh];
            float hr = ghs[nb * 384 + hh];
            float hz = ghs[nb * 384 + 128 + hh];
            float hn = ghs[nb * 384 + 256 + hh];
            float r = xla_sigmoid(ir + hr);
            float z = xla_sigmoid(iz + hz);
            float n = xla_tanh(fmaf(r, hn, inn));
            float hold = hs2[hh * 2 + nb];
            hs2[hh * 2 + nb] = fmaf(1.0f - z, n, z * hold);
        } else {
            int q = tid - 256;                        // 0..255
            if (t < 63) {
                #pragma unroll
                for (int e = 0; e < 3; e++) {
                    int idx = q + e * 256;            // 0..767
                    int nb = idx >= 384;
                    int j = idx - nb * 384;
                    gis[(t + 1) & 1][idx] =
                        g_GI[(((size_t)(b0 + nb) * 64) + (t + 1)) * 384 + j];
                }
            }
            if (q < 128) {                            // gumbel row for THIS step
                int nb = q >> 6, s = q & 63;
                ggs[q] = g_G[(((size_t)t * 256) + (b0 + nb)) * 64 + s];
            }
        }
        __syncthreads();

        // ======== Phase BC: P1 (warps 0-11) / P2+publish (warps 12-15), then P3 steal ========
        if (tid < 384) {
            if (t < 63) {
                int j = tid;
                float a0 = bhs[j];
                float a1 = a0;
                const float2* h2 = (const float2*)hs2;
                #pragma unroll 8
                for (int k = 0; k < 128; k++) {
                    float w = ws[k * 384 + j];
                    float2 h = h2[k];
                    a0 = fmaf(w, h.x, a0);
                    a1 = fmaf(w, h.y, a1);
                }
                ghs[j] = a0;
                ghs[384 + j] = a1;
            }
            // acquire gsm before stealing P3 slots
            if (lane == 0) {
                while (atomicAdd(&gsm_ready, 0) == 0) {}
            }
            __syncwarp();
            __threadfence_block();
        } else {
            int a = tid - 384;                        // 0..127
            float acc0 = 0.f, acc1 = 0.f;
            #pragma unroll
            for (int k = 0; k < 128; k++) {
                float w = g_w3T[k * 128 + a];         // coalesced, L2-hot
                acc0 = fmaf(w, hs2[k * 2 + 0], acc0); // ascending k (bit-exact)
                acc1 = fmaf(w, hs2[k * 2 + 1], acc1);
            }
            gsm[a] = acc0;
            gsm[128 + a] = acc1;
            __threadfence_block();
            asm volatile("bar.sync 3, 128;" ::: "memory");   // order warps 12-15 w.r.t. each other
            if (tid == 384) atomicExch(&gsm_ready, 1);
        }
        // ---- P3: all warps steal active slots (2 per grab, pipelined pair) ----
        {
            int len = len_sm;
            int total = 2 * len;
            for (;;) {
                int ibase = 0;
                if (lane == 0) ibase = atomicAdd(&cnt2, 2);
                ibase = __shfl_sync(0xffffffffu, ibase, 0);
                if (ibase >= total) break;
                int nb0 = (ibase >= len) ? 1 : 0;
                int s0 = lst[nb0][ibase - nb0 * len];
                const float* P0 = &g_P[(((size_t)(b0 + nb0) * 64) + s0) * 128];
                float a0 = P0[lane], a1 = P0[lane + 32], a2 = P0[lane + 64], a3 = P0[lane + 96];
                int i1 = ibase + 1;
                bool have1 = (i1 < total);
                int nb1 = 0, s1 = 0;
                float c0 = 0.f, c1 = 0.f, c2 = 0.f, c3 = 0.f;
                if (have1) {
                    nb1 = (i1 >= len) ? 1 : 0;
                    s1 = lst[nb1][i1 - nb1 * len];
                    const float* P1r = &g_P[(((size_t)(b0 + nb1) * 64) + s1) * 128];
                    c0 = P1r[lane]; c1 = P1r[lane + 32]; c2 = P1r[lane + 64]; c3 = P1r[lane + 96];
                }
                const float* gp0 = &gsm[nb0 * 128];
                float acc = v0 * xla_tanh(a0 + gp0[lane]);
                acc = fmaf(v1, xla_tanh(a1 + gp0[lane + 32]), acc);
                acc = fmaf(v2, xla_tanh(a2 + gp0[lane + 64]), acc);
                acc = fmaf(v3, xla_tanh(a3 + gp0[lane + 96]), acc);
                #pragma unroll
                for (int off = 16; off; off >>= 1)
                    acc += __shfl_down_sync(0xffffffffu, acc, off);
                if (lane == 0) sc[nb0 * 64 + s0] = acc;
                if (have1) {
                    const float* gp1 = &gsm[nb1 * 128];
                    float acc1 = v0 * xla_tanh(c0 + gp1[lane]);
                    acc1 = fmaf(v1, xla_tanh(c1 + gp1[lane + 32]), acc1);
                    acc1 = fmaf(v2, xla_tanh(c2 + gp1[lane + 64]), acc1);
                    acc1 = fmaf(v3, xla_tanh(c3 + gp1[lane + 96]), acc1);
                    #pragma unroll
                    for (int off = 16; off; off >>= 1)
                        acc1 += __shfl_down_sync(0xffffffffu, acc1, off);
                    if (lane == 0) sc[nb1 * 64 + s1] = acc1;
                }
            }
        }
        __syncthreads();

        // ======== Phase D: P4a logits + gumbel + per-warp reductions ========
        if (tid < 128) {
            int nb = tid >> 6, s = tid & 63;
            bool masked = (t == 0) ? (s != 0) : (vis[nb * 64 + s] != 0);
            float logit = masked ? NEGV : sc[tid];
            float z = masked ? NEGV : (logit + ggs[tid]);
            // warp tournament: strict > keeps lowest index among maxima (first-max)
            float bv = z; int bi_ = s;
            float ml = logit;
            #pragma unroll
            for (int off = 16; off; off >>= 1) {
                float ov = __shfl_down_sync(0xffffffffu, bv, off);
                int   oi = __shfl_down_sync(0xffffffffu, bi_, off);
                float om = __shfl_down_sync(0xffffffffu, ml, off);
                if (ov > bv) { bv = ov; bi_ = oi; }
                ml = fmaxf(ml, om);
            }
            ml = __shfl_sync(0xffffffffu, ml, 0);
            float e = __expf(logit - ml);     // masked -> exp(-1e9-m) = 0
            #pragma unroll
            for (int off = 16; off; off >>= 1) e += __shfl_down_sync(0xffffffffu, e, off);
            if (lane == 0) { wbv[wrp] = bv; wbi[wrp] = bi_; wml[wrp] = ml; wse[wrp] = e; }
        }
        __syncthreads();

        // -------- P4b: combine + output + list maintenance (overlaps next Phase A) --------
        if (tid < 2) {
            int nb = tid;
            int w0 = nb * 2;
            float va = wbv[w0], vb = wbv[w0 + 1];
            int bi = (vb > va) ? wbi[w0 + 1] : wbi[w0];   // lower-s warp wins ties
            float m = fmaxf(wml[w0], wml[w0 + 1]);
            float se = wse[w0] * __expf(wml[w0] - m) + wse[w0 + 1] * __expf(wml[w0 + 1] - m);
            float logp = sc[nb * 64 + bi] - m - __logf(se);   // chosen is always unmasked
            vis[nb * 64 + bi] = 1;
            int bg = b0 + nb;
            out[bg * 64 + t] = (float)bi;
            out[16384 + bg * 64 + t] = logp;
            // update active list for next step
            if (t == 0) {
                for (int l = 0; l < 63; l++) { lst[nb][l] = l + 1; pos[nb][l + 1] = l; }
                if (nb == 0) len_sm = 63;
            } else {
                int L = len_sm;                // both lanes read in lockstep before write
                int p = pos[nb][bi];
                int last = lst[nb][L - 1];
                lst[nb][p] = last;
                pos[nb][last] = p;
                if (nb == 0) len_sm = L - 1;
            }
        }
        // no trailing barrier: Phase A/BC barriers of step t+1 order these writes
        // before their readers (len_sm/lst in BC, vis/sc in D).
    }
}

// ---------------- launcher ----------------
extern "C" void kernel_launch(void* const* d_in, const int* in_sizes, int n_in,
                              void* d_out, int out_size) {
    const float* E     = (const float*)d_in[1];   // static_embeddings (B,H,S)
    const float* dyn   = (const float*)d_in[2];   // dynamic (B,2,S)
    const float* dyn_w = (const float*)d_in[3];
    const float* dyn_b = (const float*)d_in[4];
    const float* in_w  = (const float*)d_in[5];
    const float* in_b  = (const float*)d_in[6];
    const float* w_ih  = (const float*)d_in[7];
    const float* w_hh  = (const float*)d_in[8];
    const float* b_ih  = (const float*)d_in[9];
    const float* b_hh  = (const float*)d_in[10];
    const float* W_att = (const float*)d_in[11];
    const float* v_att = (const float*)d_in[12];
    float* out = (float*)d_out;

    cudaFuncSetAttribute(main_kernel,   cudaFuncAttributeMaxDynamicSharedMemorySize, 196608);
    cudaFuncSetAttribute(xchain_kernel, cudaFuncAttributeMaxDynamicSharedMemorySize, 65536);

    prep_kernel<<<64, 256>>>(dyn_w, dyn_b, in_w, w_ih, w_hh, W_att);
    gumbel_kernel<<<4096, 256>>>();
    xchain_kernel<<<256, 128, 65536>>>(E, in_b);
    gi_kernel<<<dim3(256, 6), 256>>>(b_ih);
    p_kernel<<<dim3(256, 2), 256>>>(E, dyn);
    main_kernel<<<128, 512, 196608>>>(b_hh, v_att, out);
}

// round 16
// speedup vs baseline: 1.7778x; 1.7778x over previous
#include <cuda_runtime.h>
#include <cuda_bf16.h>
#include <cstdint>

// ---------------- constants ----------------
#define NEGV -1e9f
#define TINYF 1.17549435e-38f

// ---------------- device scratch (static allocation only) ----------------
__device__ float g_inwT[128 * 128];     // in_w^T   [k][h]
__device__ float g_wihT[128 * 384];     // w_ih^T   [k][j]
__device__ float g_whhT[128 * 384];     // w_hh^T   [k][j]
__device__ float g_w1T [128 * 128];     // W_att[:,0:128]^T   [k][a]
__device__ float g_w3T [128 * 128];     // W_att[:,256:384]^T [k][a]
__device__ float g_M   [128 * 2];       // W2 @ dyn_w   [a][d]
__device__ float g_c2  [128];           // W2 @ dyn_b   [a]
__device__ unsigned g_fk0[64], g_fk1[64];
__device__ float g_X [256 * 64 * 128];  // x_t  [b][t][h]
__device__ float g_GI[256 * 64 * 384];  // gi_t [b][t][j]
__device__ float g_P [256 * 64 * 128];  // [b][s][a] step-invariant attention pre-act
__device__ float g_G [64 * 256 * 64];   // [t][b][s] gumbel term  (-log(-log(u)))

// ---------------- threefry-2x32 (20 rounds, JAX-exact) ----------------
__device__ __forceinline__ unsigned rotl32(unsigned x, int r) {
    return (x << r) | (x >> (32 - r));
}
__device__ __forceinline__ void tf2x32(unsigned k0, unsigned k1,
                                       unsigned x0, unsigned x1,
                                       unsigned& o0, unsigned& o1) {
    unsigned k2 = k0 ^ k1 ^ 0x1BD11BDAu;
    x0 += k0; x1 += k1;
    const int ra0 = 13, ra1 = 15, ra2 = 26, ra3 = 6;
    const int rb0 = 17, rb1 = 29, rb2 = 16, rb3 = 24;
#define TFR(r) { x0 += x1; x1 = rotl32(x1, r); x1 ^= x0; }
    TFR(ra0) TFR(ra1) TFR(ra2) TFR(ra3)
    x0 += k1; x1 += k2 + 1u;
    TFR(rb0) TFR(rb1) TFR(rb2) TFR(rb3)
    x0 += k2; x1 += k0 + 2u;
    TFR(ra0) TFR(ra1) TFR(ra2) TFR(ra3)
    x0 += k0; x1 += k1 + 3u;
    TFR(rb0) TFR(rb1) TFR(rb2) TFR(rb3)
    x0 += k1; x1 += k2 + 4u;
    TFR(ra0) TFR(ra1) TFR(ra2) TFR(ra3)
    x0 += k2; x1 += k0 + 5u;
#undef TFR
    o0 = x0; o1 = x1;
}

// ---------------- XLA-exact f32 tanh (Eigen rational) + logistic ----------------
__device__ __forceinline__ float xla_tanh(float x) {
    float ax = fabsf(x);
    float xc = fminf(fmaxf(x, -7.90531110763549805f), 7.90531110763549805f);
    float x2 = xc * xc;
    float p = fmaf(x2, -2.76076847742355e-16f, 2.00018790482477e-13f);
    p = fmaf(x2, p, -8.60467152213735e-11f);
    p = fmaf(x2, p,  5.12229709037114e-08f);
    p = fmaf(x2, p,  1.48572235717979e-05f);
    p = fmaf(x2, p,  6.37261928875436e-04f);
    p = fmaf(x2, p,  4.89352455891786e-03f);
    p = p * xc;
    float q = fmaf(x2, 1.19825839466702e-06f, 1.18534705686654e-04f);
    q = fmaf(x2, q, 2.26843463243900e-03f);
    q = fmaf(x2, q, 4.89352518554385e-03f);
    float r = __fdiv_rn(p, q);
    return (ax < 4.0e-4f) ? x : r;
}
__device__ __forceinline__ float xla_sigmoid(float x) {
    return 0.5f + 0.5f * xla_tanh(0.5f * x);
}

// ---------------- kernel 0: weight prep ----------------
__global__ void prep_kernel(const float* __restrict__ dyn_w, const float* __restrict__ dyn_b,
                            const float* __restrict__ in_w, const float* __restrict__ w_ih,
                            const float* __restrict__ w_hh, const float* __restrict__ W_att) {
    int tid = blockIdx.x * blockDim.x + threadIdx.x;
    int nt = gridDim.x * blockDim.x;
    for (int i = tid; i < 128 * 128; i += nt) {
        int h = i >> 7, k = i & 127;
        g_inwT[k * 128 + h] = in_w[i];
    }
    for (int i = tid; i < 384 * 128; i += nt) {
        int j = i >> 7, k = i & 127;
        g_wihT[k * 384 + j] = w_ih[i];
        g_whhT[k * 384 + j] = w_hh[i];
    }
    for (int i = tid; i < 128 * 128; i += nt) {
        int a = i >> 7, k = i & 127;
        g_w1T[k * 128 + a] = W_att[a * 384 + k];
        g_w3T[k * 128 + a] = W_att[a * 384 + 256 + k];
    }
    for (int i = tid; i < 128 * 2; i += nt) {
        int a = i >> 1, d = i & 1;
        float s = 0.f;
        for (int k = 0; k < 128; k++) s = fmaf(W_att[a * 384 + 128 + k], dyn_w[k * 2 + d], s);
        g_M[i] = s;
    }
    for (int i = tid; i < 128; i += nt) {
        float s = 0.f;
        for (int k = 0; k < 128; k++) s = fmaf(W_att[i * 384 + 128 + k], dyn_b[k], s);
        g_c2[i] = s;
    }
    if (tid < 64) {
        unsigned o0, o1;
        tf2x32(0u, 42u, 0u, (unsigned)tid, o0, o1);  // fold_in(key(42), t)
        g_fk0[tid] = o0; g_fk1[tid] = o1;
    }
}

// ---------------- kernel 0b: gumbel precompute (mask-independent) ----------------
__global__ void gumbel_kernel() {
    int i = blockIdx.x * blockDim.x + threadIdx.x;    // 0 .. 1048575
    int t = i >> 14;
    unsigned bs = (unsigned)(i & 16383);              // counter = b*64 + s
    unsigned o0, o1;
    tf2x32(g_fk0[t], g_fk1[t], 0u, bs, o0, o1);
    unsigned bits = o0 ^ o1;
    float f = __uint_as_float((bits >> 9) | 0x3f800000u) - 1.0f;
    float u = (f == 0.f) ? TINYF : f;
    float l1 = (float)log((double)u);
    float l2 = (float)log((double)(-l1));
    g_G[i] = -l2;                                     // z = logit + g_G  (== logit - l2)
}

// ---------------- kernel 1: x-chain (in_w SMEM-resident) ----------------
__global__ void xchain_kernel(const float* __restrict__ E, const float* __restrict__ in_b) {
    extern __shared__ float sw[];        // 16384 floats = 64KB inwT copy
    __shared__ float xs[128];
    int b = blockIdx.x;
    int h = threadIdx.x;                 // 128 threads
    for (int i = h; i < 16384; i += 128) sw[i] = g_inwT[i];
    xs[h] = E[b * 8192 + h * 64 + 0];    // static_embeddings[b, h, 0]
    float bb = in_b[h];
    __syncthreads();
    for (int t = 0; t < 64; t++) {
        float acc = bb;
        #pragma unroll 8
        for (int k = 0; k < 128; k++) acc = fmaf(sw[k * 128 + h], xs[k], acc);
        __syncthreads();
        xs[h] = acc;
        g_X[(b * 64 + t) * 128 + h] = acc;
        __syncthreads();
    }
}

// ---------------- kernel 2: GI = X @ w_ih^T + b_ih  (grid 256 x 6) ----------------
__global__ void gi_kernel(const float* __restrict__ b_ih) {
    __shared__ float Xs[64 * 128];
    int blk = blockIdx.x;
    int c   = blockIdx.y;
    for (int i = threadIdx.x; i < 8192; i += 256) Xs[i] = g_X[blk * 8192 + i];
    __syncthreads();
    int jl = threadIdx.x & 63;
    int btb = (threadIdx.x >> 6) * 16;
    int j = jl + 64 * c;
    float acc[16];
    #pragma unroll
    for (int r = 0; r < 16; r++) acc[r] = 0.f;
    for (int k = 0; k < 128; k += 4) {
        float w0 = g_wihT[(k + 0) * 384 + j];
        float w1 = g_wihT[(k + 1) * 384 + j];
        float w2 = g_wihT[(k + 2) * 384 + j];
        float w3 = g_wihT[(k + 3) * 384 + j];
        #pragma unroll
        for (int r = 0; r < 16; r++) {
            float4 x = *(const float4*)&Xs[(btb + r) * 128 + k];
            acc[r] = fmaf(w0, x.x, acc[r]);   // ascending k per accumulator
            acc[r] = fmaf(w1, x.y, acc[r]);
            acc[r] = fmaf(w2, x.z, acc[r]);
            acc[r] = fmaf(w3, x.w, acc[r]);
        }
    }
    float bb = b_ih[j];
    #pragma unroll
    for (int r = 0; r < 16; r++)
        g_GI[(size_t)(blk * 64 + btb + r) * 384 + j] = acc[r] + bb;
}

// ---------------- kernel 3: P[b][s][a] (grid 256 x 2) ----------------
__global__ void p_kernel(const float* __restrict__ E, const float* __restrict__ dyn) {
    __shared__ float Es[128 * 32];
    int b = blockIdx.x;
    int sh = blockIdx.y;                     // s half (0/1)
    for (int i = threadIdx.x; i < 4096; i += 256) {
        int k = i >> 5, s2 = i & 31;
        Es[i] = E[b * 8192 + k * 64 + sh * 32 + s2];
    }
    __syncthreads();
    int a = threadIdx.x & 127;
    int sq = (threadIdx.x >> 7) * 16;        // 16 s per thread
    float acc[16];
    #pragma unroll
    for (int ss = 0; ss < 16; ss++) acc[ss] = 0.f;
    for (int k = 0; k < 128; k++) {
        float w = g_w1T[k * 128 + a];
        const float4* e4 = (const float4*)&Es[k * 32 + sq];
        #pragma unroll
        for (int q = 0; q < 4; q++) {
            float4 e = e4[q];
            acc[q * 4 + 0] = fmaf(w, e.x, acc[q * 4 + 0]);
            acc[q * 4 + 1] = fmaf(w, e.y, acc[q * 4 + 1]);
            acc[q * 4 + 2] = fmaf(w, e.z, acc[q * 4 + 2]);
            acc[q * 4 + 3] = fmaf(w, e.w, acc[q * 4 + 3]);
        }
    }
    float m0 = g_M[a * 2], m1 = g_M[a * 2 + 1], c = g_c2[a];
    #pragma unroll
    for (int ss = 0; ss < 16; ss++) {
        int s = sh * 32 + sq + ss;
        float v = acc[ss] + fmaf(m0, dyn[b * 128 + s], fmaf(m1, dyn[b * 128 + 64 + s], c));
        g_P[((size_t)b * 64 + s) * 128 + a] = v;
    }
}

// ---------------- P4: full sampling for step tt (one warp per batch) ----------------
// lane owns slot pair {2*lane, 2*lane+1}; strict-> pair pick + tree over
// contiguous lane ranges == linear first-max (tours exact).
__device__ __forceinline__ void do_p4(
    int tt, int nb, int lane, int b0,
    const float* sc, int* vis, int (*lst)[64], int (*pos)[64], int* len2,
    float* out)
{
    int s0 = lane * 2, s1 = s0 + 1;
    float2 gg = *(const float2*)&g_G[(((size_t)tt * 256) + (b0 + nb)) * 64 + s0];
    bool m0 = (tt == 0) ? (s0 != 0) : (vis[nb * 64 + s0] != 0);
    bool m1 = (tt == 0) ? (s1 != 0) : (vis[nb * 64 + s1] != 0);
    float l0 = m0 ? NEGV : sc[nb * 64 + s0];
    float l1 = m1 ? NEGV : sc[nb * 64 + s1];
    float z0 = m0 ? NEGV : (l0 + gg.x);
    float z1 = m1 ? NEGV : (l1 + gg.y);
    float bv; int bi;
    if (z1 > z0) { bv = z1; bi = s1; } else { bv = z0; bi = s0; }
    float ml = fmaxf(l0, l1);
    #pragma unroll
    for (int off = 16; off; off >>= 1) {
        float ov = __shfl_down_sync(0xffffffffu, bv, off);
        int   oi = __shfl_down_sync(0xffffffffu, bi, off);
        float om = __shfl_down_sync(0xffffffffu, ml, off);
        if (ov > bv) { bv = ov; bi = oi; }
        ml = fmaxf(ml, om);
    }
    ml = __shfl_sync(0xffffffffu, ml, 0);
    float e = __expf(l0 - ml) + __expf(l1 - ml);   // masked -> 0
    #pragma unroll
    for (int off = 16; off; off >>= 1) e += __shfl_down_sync(0xffffffffu, e, off);
    if (tt == 0) {
        for (int l = lane; l < 63; l += 32) { lst[nb][l] = l + 1; pos[nb][l + 1] = l; }
    }
    if (lane == 0) {
        float logp = sc[nb * 64 + bi] - ml - __logf(e);
        vis[nb * 64 + bi] = 1;
        int bg = b0 + nb;
        out[bg * 64 + tt] = (float)bi;
        out[16384 + bg * 64 + tt] = logp;
        if (tt == 0) {
            len2[nb] = 63;
        } else {
            int L = len2[nb];
            int p = pos[nb][bi];
            int last = lst[nb][L - 1];
            lst[nb][p] = last;
            pos[nb][last] = p;
            len2[nb] = L - 1;
        }
    }
}

// ---------------- kernel 4: sequential decode (2 batches/CTA, 512 threads) ----------------
// Per-step schedule (3 barriers):
//   A : GRU_t (warps 0-7)  ||  P4_{t-1} (warps 8-9)  ||  prefetch GI_{t+1} (warps 10-15)
//   B : P1 gh_{t+1} (warps 0-11)  ||  P2_t -> gsm (warps 12-15)
//   C : P3_t scores, all warps, slot pairs with interleaved reductions
__global__ void __launch_bounds__(512, 1)
main_kernel(const float* __restrict__ b_hh, const float* __restrict__ v_att,
            float* __restrict__ out) {
    extern __shared__ float ws[];            // whhT copy: 49152 floats (196608 B)
    __shared__ float hs2[2 * 128];           // h interleaved: hs2[2*h + nb]
    __shared__ float ghs[2 * 384];
    __shared__ float gsm[2 * 128];
    __shared__ float sc[128];
    __shared__ float vsm[128];
    __shared__ float bhs[384];
    __shared__ float gis[2][768];            // double-buffered GI rows
    __shared__ int   vis[128];
    __shared__ int   lst[2][64];             // compacted active slot lists
    __shared__ int   pos[2][64];             // s -> list index
    __shared__ int   len2[2];

    int tid = threadIdx.x;
    int b0 = blockIdx.x * 2;
    const int wrp = tid >> 5, lane = tid & 31;

    for (int i = tid; i < 49152; i += 512) ws[i] = g_whhT[i];
    if (tid < 384) bhs[tid] = b_hh[tid];
    if (tid < 128) { vsm[tid] = v_att[tid]; vis[tid] = 0; }
    if (tid < 256) hs2[tid] = 0.f;
    if (tid < 2) { lst[tid][0] = 0; pos[tid][0] = 0; len2[tid] = 1; }
    __syncthreads();                          // bhs visible
    // gh_0 = b_hh exactly (h0 = 0, fmaf(w,0,acc)=acc)
    if (tid < 384) { ghs[tid] = bhs[tid]; ghs[384 + tid] = bhs[tid]; }
    // preload gis[0] = GI rows at t=0
    for (int i = tid; i < 768; i += 512) {
        int nb = i >= 384; int j = i - nb * 384;
        gis[0][i] = g_GI[(((size_t)(b0 + nb) * 64) + 0) * 384 + j];
    }
    __syncthreads();

    const float v0 = vsm[lane], v1 = vsm[lane + 32], v2 = vsm[lane + 64], v3 = vsm[lane + 96];

    for (int t = 0; t < 64; t++) {
        // ======== Phase A: GRU_t (w0-7)  ||  P4_{t-1} (w8-9)  ||  prefetch (w10-15) ========
        if (tid < 256) {
            int nb = tid >> 7, hh = tid & 127;
            const float* gi_ = &gis[t & 1][nb * 384];
            float ir = gi_[hh];
            float iz = gi_[128 + hh];
            float inn = gi_[256 + hh];
            float hr = ghs[nb * 384 + hh];
            float hz = ghs[nb * 384 + 128 + hh];
            float hn = ghs[nb * 384 + 256 + hh];
            float r = xla_sigmoid(ir + hr);
            float z = xla_sigmoid(iz + hz);
            float n = xla_tanh(fmaf(r, hn, inn));
            float hold = hs2[hh * 2 + nb];
            hs2[hh * 2 + nb] = fmaf(1.0f - z, n, z * hold);
        } else if (tid < 320) {
            // P4 for previous step (sc_{t-1} sealed by C_{t-1} barrier)
            if (t > 0) do_p4(t - 1, wrp - 8, lane, b0, sc, vis, lst, pos, len2, out);
        } else {
            if (t < 63) {
                int q = tid - 320;                        // 0..191
                #pragma unroll
                for (int e = 0; e < 4; e++) {
                    int idx = q + e * 192;                // 0..767
                    int nb = idx >= 384;
                    int j = idx - nb * 384;
                    gis[(t + 1) & 1][idx] =
                        g_GI[(((size_t)(b0 + nb) * 64) + (t + 1)) * 384 + j];
                }
            }
        }
        __syncthreads();

        // ======== Phase B: P1 gh_{t+1} (warps 0-11)  ||  P2_t (warps 12-15) ========
        if (tid < 384) {
            if (t < 63) {
                int j = tid;
                float a0 = bhs[j];
                float a1 = a0;
                const float2* h2 = (const float2*)hs2;
                #pragma unroll 8
                for (int k = 0; k < 128; k++) {
                    float w = ws[k * 384 + j];
                    float2 h = h2[k];
                    a0 = fmaf(w, h.x, a0);
                    a1 = fmaf(w, h.y, a1);
                }
                ghs[j] = a0;
                ghs[384 + j] = a1;
            }
        } else {
            int a = tid - 384;                        // 0..127
            float acc0 = 0.f, acc1 = 0.f;
            #pragma unroll
            for (int k = 0; k < 128; k++) {
                float w = g_w3T[k * 128 + a];         // coalesced, L2-hot
                acc0 = fmaf(w, hs2[k * 2 + 0], acc0); // ascending k (bit-exact)
                acc1 = fmaf(w, hs2[k * 2 + 1], acc1);
            }
            gsm[a] = acc0;
            gsm[128 + a] = acc1;
        }
        __syncthreads();

        // ======== Phase C: P3_t, slot pairs (i, i+16), interleaved reductions ========
        {
            int len = len2[0];                        // both batches same length
            int total = 2 * len;
            for (int i = wrp; i < total; i += 32) {
                int i1 = i + 16;
                bool have1 = (i1 < total);
                int nb0 = (i >= len) ? 1 : 0;
                int s0 = lst[nb0][i - nb0 * len];
                const float* P0 = &g_P[(((size_t)(b0 + nb0) * 64) + s0) * 128];
                float a0 = P0[lane], a1 = P0[lane + 32], a2 = P0[lane + 64], a3 = P0[lane + 96];
                int nb1 = 0, s1 = 0;
                float c0 = 0.f, c1 = 0.f, c2 = 0.f, c3 = 0.f;
                if (have1) {
                    nb1 = (i1 >= len) ? 1 : 0;
                    s1 = lst[nb1][i1 - nb1 * len];
                    const float* P1r = &g_P[(((size_t)(b0 + nb1) * 64) + s1) * 128];
                    c0 = P1r[lane]; c1 = P1r[lane + 32]; c2 = P1r[lane + 64]; c3 = P1r[lane + 96];
                }
                const float* gp0 = &gsm[nb0 * 128];
                float acc0 = v0 * xla_tanh(a0 + gp0[lane]);
                acc0 = fmaf(v1, xla_tanh(a1 + gp0[lane + 32]), acc0);
                acc0 = fmaf(v2, xla_tanh(a2 + gp0[lane + 64]), acc0);
                acc0 = fmaf(v3, xla_tanh(a3 + gp0[lane + 96]), acc0);
                float acc1 = 0.f;
                if (have1) {
                    const float* gp1 = &gsm[nb1 * 128];
                    acc1 = v0 * xla_tanh(c0 + gp1[lane]);
                    acc1 = fmaf(v1, xla_tanh(c1 + gp1[lane + 32]), acc1);
                    acc1 = fmaf(v2, xla_tanh(c2 + gp1[lane + 64]), acc1);
                    acc1 = fmaf(v3, xla_tanh(c3 + gp1[lane + 96]), acc1);
                }
                // interleaved warp reductions: the two shfl chains overlap
                #pragma unroll
                for (int off = 16; off; off >>= 1) {
                    acc0 += __shfl_down_sync(0xffffffffu, acc0, off);
                    acc1 += __shfl_down_sync(0xffffffffu, acc1, off);
                }
                if (lane == 0) {
                    sc[nb0 * 64 + s0] = acc0;
                    if (have1) sc[nb1 * 64 + s1] = acc1;
                }
            }
        }
        __syncthreads();
    }

    // final sampling for t=63 (sc_63 sealed by last C barrier)
    if (tid < 64) do_p4(63, wrp, lane, b0, sc, vis, lst, pos, len2, out);
}

// ---------------- launcher ----------------
extern "C" void kernel_launch(void* const* d_in, const int* in_sizes, int n_in,
                              void* d_out, int out_size) {
    const float* E     = (const float*)d_in[1];   // static_embeddings (B,H,S)
    const float* dyn   = (const float*)d_in[2];   // dynamic (B,2,S)
    const float* dyn_w = (const float*)d_in[3];
    const float* dyn_b = (const float*)d_in[4];
    const float* in_w  = (const float*)d_in[5];
    const float* in_b  = (const float*)d_in[6];
    const float* w_ih  = (const float*)d_in[7];
    const float* w_hh  = (const float*)d_in[8];
    const float* b_ih  = (const float*)d_in[9];
    const float* b_hh  = (const float*)d_in[10];
    const float* W_att = (const float*)d_in[11];
    const float* v_att = (const float*)d_in[12];
    float* out = (float*)d_out;

    cudaFuncSetAttribute(main_kernel,   cudaFuncAttributeMaxDynamicSharedMemorySize, 196608);
    cudaFuncSetAttribute(xchain_kernel, cudaFuncAttributeMaxDynamicSharedMemorySize, 65536);

    prep_kernel<<<64, 256>>>(dyn_w, dyn_b, in_w, w_ih, w_hh, W_att);
    gumbel_kernel<<<4096, 256>>>();
    xchain_kernel<<<256, 128, 65536>>>(E, in_b);
    gi_kernel<<<dim3(256, 6), 256>>>(b_ih);
    p_kernel<<<dim3(256, 2), 256>>>(E, dyn);
    main_kernel<<<128, 512, 196608>>>(b_hh, v_att, out);
}